// round 6
// baseline (speedup 1.0000x reference)
#include <cuda_runtime.h>
#include <math.h>

// Problem constants (fixed by the reference)
#define POOL   100
#define NTASKS 10
#define NB_PT  (POOL / NTASKS)       // 10
#define PLEN   8
#define EMBD   768
#define BATCH  512
#define ED4    (EMBD / 4)            // 192

#define SIM_GROUPS  8                // 64 batch rows per group
#define SIM_BLOCKS  (NB_PT * SIM_GROUPS)   // 80
#define COPY_BLOCKS 2560
#define PMT_BLOCKS  BATCH            // 512
#define ROWS_PER_W  (BATCH / SIM_GROUPS / 8)  // 8 rows per warp

// Scratch (allocation-free; zero-init at module load, restored to 0 each launch)
__device__ float    g_sim[BATCH * POOL];
__device__ unsigned g_done;
__device__ unsigned g_pmt_done;

// ---------------------------------------------------------------------------
// One kernel, three roles by blockIdx.x:
//   [0, 80):          sim producers  (diag in smem once per k, 64 b-rows each)
//   [80, 2640):       streaming copy (x_block -> out tail)
//   [2640, 3152):     pmt consumers  (spin on g_done, then einsum)
// ---------------------------------------------------------------------------
__global__ void __launch_bounds__(256) mega_kernel(
        const float* __restrict__ x_querry,
        const float* __restrict__ e_a,
        const float* __restrict__ e_p,
        const float* __restrict__ x_block,
        const int*   __restrict__ task_id_p,
        float* __restrict__ out,
        size_t xb_float4s) {
    __shared__ float s_diag[EMBD];
    __shared__ float s_ea[EMBD];

    const int tid  = threadIdx.x;
    const int warp = tid >> 5;
    const int lane = tid & 31;

    if (blockIdx.x >= SIM_BLOCKS && blockIdx.x < SIM_BLOCKS + COPY_BLOCKS) {
        // ================= streaming copy =================
        const float4* src = (const float4*)x_block;
        float4* dst = (float4*)(out + (size_t)BATCH * PLEN * EMBD);

        const size_t stride = (size_t)COPY_BLOCKS * 256;
        size_t i = (size_t)(blockIdx.x - SIM_BLOCKS) * 256 + tid;

        for (; i + 7 * stride < xb_float4s; i += 8 * stride) {
            float4 v0 = __ldcs(src + i);
            float4 v1 = __ldcs(src + i + stride);
            float4 v2 = __ldcs(src + i + 2 * stride);
            float4 v3 = __ldcs(src + i + 3 * stride);
            float4 v4 = __ldcs(src + i + 4 * stride);
            float4 v5 = __ldcs(src + i + 5 * stride);
            float4 v6 = __ldcs(src + i + 6 * stride);
            float4 v7 = __ldcs(src + i + 7 * stride);
            __stcs(dst + i,              v0);
            __stcs(dst + i + stride,     v1);
            __stcs(dst + i + 2 * stride, v2);
            __stcs(dst + i + 3 * stride, v3);
            __stcs(dst + i + 4 * stride, v4);
            __stcs(dst + i + 5 * stride, v5);
            __stcs(dst + i + 6 * stride, v6);
            __stcs(dst + i + 7 * stride, v7);
        }
        for (; i < xb_float4s; i += stride)
            __stcs(dst + i, __ldcs(src + i));
        return;
    }

    const int task_end = (*task_id_p + 1) * NB_PT;

    if (blockIdx.x < SIM_BLOCKS) {
        // ================= sim producers =================
        const int kslot = blockIdx.x % NB_PT;       // 0..9
        const int group = blockIdx.x / NB_PT;       // 0..7
        const int b0 = group * (BATCH / SIM_GROUPS);

        for (int k = kslot; k < task_end; k += NB_PT) {
            __syncthreads();   // protect smem across k iterations
            // diag[k][:] and e_a[k][:] into smem
            const float* epk = e_p + (size_t)k * PLEN * EMBD;
            for (int d = tid; d < EMBD; d += 256) {
                float acc = 0.f;
#pragma unroll
                for (int l = 0; l < PLEN; l++) {
                    float v = epk[l * EMBD + d];
                    acc += v * v;
                }
                s_diag[d] = acc;
                s_ea[d]   = e_a[(size_t)k * EMBD + d];
            }
            __syncthreads();

            const int row = POOL - task_end + k;
            const float4* ea4 = (const float4*)s_ea;
            const float4* dg4 = (const float4*)s_diag;

            for (int rr = 0; rr < ROWS_PER_W; rr++) {
                const int b = b0 + warp * ROWS_PER_W + rr;
                const float4* xq4 = (const float4*)(x_querry +
                                    ((size_t)b * POOL + row) * EMBD);
                float s1 = 0.f, s2 = 0.f, s3 = 0.f;
#pragma unroll
                for (int j = 0; j < ED4 / 32; j++) {   // 6 iterations
                    int idx = lane + j * 32;
                    float4 x = xq4[idx];
                    float4 e = ea4[idx];
                    float4 g = dg4[idx];
                    float a, aa;
                    a = x.x * e.x; aa = a * a; s3 += aa; s1 += aa * g.x; s2 += aa * g.x * g.x;
                    a = x.y * e.y; aa = a * a; s3 += aa; s1 += aa * g.y; s2 += aa * g.y * g.y;
                    a = x.z * e.z; aa = a * a; s3 += aa; s1 += aa * g.z; s2 += aa * g.z * g.z;
                    a = x.w * e.w; aa = a * a; s3 += aa; s1 += aa * g.w; s2 += aa * g.w * g.w;
                }
#pragma unroll
                for (int o = 16; o > 0; o >>= 1) {
                    s1 += __shfl_down_sync(0xFFFFFFFFu, s1, o);
                    s2 += __shfl_down_sync(0xFFFFFFFFu, s2, o);
                    s3 += __shfl_down_sync(0xFFFFFFFFu, s3, o);
                }
                if (lane == 0) {
                    const float eps = 1e-12f;
                    float n1 = fmaxf(sqrtf(s2), eps);
                    float n2 = fmaxf(sqrtf(s3), eps);
                    g_sim[(size_t)b * POOL + k] = s1 / (n1 * n2);
                }
            }
        }

        __threadfence();       // make g_sim stores device-visible
        __syncthreads();       // all warps done
        if (tid == 0) atomicAdd(&g_done, 1u);
        return;
    }

    // ================= pmt consumers =================
    if (tid == 0) {
        while (atomicAdd(&g_done, 0u) < SIM_BLOCKS) __nanosleep(64);
    }
    __syncthreads();
    __threadfence();           // acquire: see producers' g_sim stores

    const int b = blockIdx.x - (SIM_BLOCKS + COPY_BLOCKS);

    __shared__ float s_sim[POOL];
    if (tid < POOL)
        s_sim[tid] = g_sim[(size_t)b * POOL + tid];
    __syncthreads();

    const float4* ep4 = (const float4*)e_p;
    const size_t KEY4 = (size_t)BATCH * (PLEN / 2) * ED4;

    // PLEN*ED4 = 1536 float4 outputs per b; 256 threads -> 6 each
    for (int idx = tid; idx < PLEN * ED4; idx += 256) {
        int l  = idx / ED4;
        int d4 = idx % ED4;
        float4 acc = make_float4(0.f, 0.f, 0.f, 0.f);
        for (int kk = 0; kk < task_end; kk++) {
            float s  = s_sim[kk];
            float4 v = ep4[((size_t)kk * PLEN + l) * ED4 + d4];
            acc.x += s * v.x; acc.y += s * v.y;
            acc.z += s * v.z; acc.w += s * v.w;
        }
        float4* o4;
        if (l < PLEN / 2)
            o4 = (float4*)out + ((size_t)b * (PLEN / 2) + l) * ED4 + d4;
        else
            o4 = (float4*)out + KEY4 +
                 ((size_t)b * (PLEN / 2) + (l - PLEN / 2)) * ED4 + d4;
        *o4 = acc;
    }

    // Replay-safe reset: last pmt block to finish zeroes the counters.
    __syncthreads();
    if (tid == 0) {
        __threadfence();
        unsigned t = atomicAdd(&g_pmt_done, 1u);
        if (t == PMT_BLOCKS - 1) {
            atomicExch(&g_pmt_done, 0u);
            atomicExch(&g_done, 0u);
        }
    }
}

// ---------------------------------------------------------------------------
// Launch — one kernel, dependencies resolved in-kernel.
// Inputs (metadata order): x_querry, x_block, e_a, e_p, idx, task_id
// ---------------------------------------------------------------------------
extern "C" void kernel_launch(void* const* d_in, const int* in_sizes, int n_in,
                              void* d_out, int out_size) {
    const float* x_querry = (const float*)d_in[0];
    const float* x_block  = (const float*)d_in[1];
    const float* e_a      = (const float*)d_in[2];
    const float* e_p      = (const float*)d_in[3];
    const int*   task_id  = (const int*)d_in[5];
    float* out = (float*)d_out;

    size_t xb_float4s = (size_t)in_sizes[1] / 4;
    mega_kernel<<<SIM_BLOCKS + COPY_BLOCKS + PMT_BLOCKS, 256>>>(
        x_querry, e_a, e_p, x_block, task_id, out, xb_float4s);
}

// round 7
// speedup vs baseline: 1.0199x; 1.0199x over previous
#include <cuda_runtime.h>
#include <math.h>

// Problem constants (fixed by the reference)
#define POOL   100
#define NTASKS 10
#define NB_PT  (POOL / NTASKS)       // 10
#define PLEN   8
#define EMBD   768
#define BATCH  512
#define ED4    (EMBD / 4)            // 192

#define SIM_GROUPS  8                // 64 batch rows per group
#define SIM_BLOCKS  (NB_PT * SIM_GROUPS)   // 80
#define COPY_BLOCKS 2560
#define PMT_BLOCKS  BATCH            // 512
#define ROWS_PER_W  (BATCH / SIM_GROUPS / 8)  // 8 rows per warp

// Scratch (allocation-free; zero-init at module load, reset to 0 each launch)
__device__ float    g_sim[BATCH * POOL];
__device__ unsigned g_done;
__device__ unsigned g_pmt_done;

// ---------------------------------------------------------------------------
// One kernel, three roles by blockIdx.x:
//   [0, 80):       sim producers  (diag in smem once per k, 64 b-rows each)
//   [80, 2640):    streaming copy (x_block -> out tail)
//   [2640, 3152):  pmt consumers  (spin on g_done, then einsum)
// Register-capped so the copy path keeps occupancy (the controlling variable:
// regs 40-48 => 76% DRAM; regs 70 => 70%; regs 170 => 49%).
// ---------------------------------------------------------------------------
__global__ void __launch_bounds__(256, 5) mega_kernel(
        const float* __restrict__ x_querry,
        const float* __restrict__ e_a,
        const float* __restrict__ e_p,
        const float* __restrict__ x_block,
        const int*   __restrict__ task_id_p,
        float* __restrict__ out,
        size_t xb_float4s) {
    __shared__ float s_diag[EMBD];
    __shared__ float s_ea[EMBD];

    const int tid  = threadIdx.x;
    const int warp = tid >> 5;
    const int lane = tid & 31;

    if (blockIdx.x >= SIM_BLOCKS && blockIdx.x < SIM_BLOCKS + COPY_BLOCKS) {
        // ================= streaming copy =================
        const float4* src = (const float4*)x_block;
        float4* dst = (float4*)(out + (size_t)BATCH * PLEN * EMBD);

        const size_t stride = (size_t)COPY_BLOCKS * 256;
        size_t i = (size_t)(blockIdx.x - SIM_BLOCKS) * 256 + tid;

        // 4-way independent unroll (measured best: 6041 GB/s in round 2)
        for (; i + 3 * stride < xb_float4s; i += 4 * stride) {
            float4 v0 = __ldcs(src + i);
            float4 v1 = __ldcs(src + i + stride);
            float4 v2 = __ldcs(src + i + 2 * stride);
            float4 v3 = __ldcs(src + i + 3 * stride);
            __stcs(dst + i,              v0);
            __stcs(dst + i + stride,     v1);
            __stcs(dst + i + 2 * stride, v2);
            __stcs(dst + i + 3 * stride, v3);
        }
        for (; i < xb_float4s; i += stride)
            __stcs(dst + i, __ldcs(src + i));
        return;
    }

    const int task_end = (*task_id_p + 1) * NB_PT;

    if (blockIdx.x < SIM_BLOCKS) {
        // ================= sim producers =================
        const int kslot = blockIdx.x % NB_PT;       // 0..9
        const int group = blockIdx.x / NB_PT;       // 0..7
        const int b0 = group * (BATCH / SIM_GROUPS);

        for (int k = kslot; k < task_end; k += NB_PT) {
            __syncthreads();   // protect smem across k iterations
            // diag[k][:] and e_a[k][:] into smem
            const float* epk = e_p + (size_t)k * PLEN * EMBD;
            for (int d = tid; d < EMBD; d += 256) {
                float acc = 0.f;
#pragma unroll
                for (int l = 0; l < PLEN; l++) {
                    float v = epk[l * EMBD + d];
                    acc += v * v;
                }
                s_diag[d] = acc;
                s_ea[d]   = e_a[(size_t)k * EMBD + d];
            }
            __syncthreads();

            const int row = POOL - task_end + k;
            const float4* ea4 = (const float4*)s_ea;
            const float4* dg4 = (const float4*)s_diag;

            for (int rr = 0; rr < ROWS_PER_W; rr++) {
                const int b = b0 + warp * ROWS_PER_W + rr;
                const float4* xq4 = (const float4*)(x_querry +
                                    ((size_t)b * POOL + row) * EMBD);
                float s1 = 0.f, s2 = 0.f, s3 = 0.f;
#pragma unroll
                for (int j = 0; j < ED4 / 32; j++) {   // 6 iterations
                    int idx = lane + j * 32;
                    float4 x = xq4[idx];
                    float4 e = ea4[idx];
                    float4 g = dg4[idx];
                    float a, aa;
                    a = x.x * e.x; aa = a * a; s3 += aa; s1 += aa * g.x; s2 += aa * g.x * g.x;
                    a = x.y * e.y; aa = a * a; s3 += aa; s1 += aa * g.y; s2 += aa * g.y * g.y;
                    a = x.z * e.z; aa = a * a; s3 += aa; s1 += aa * g.z; s2 += aa * g.z * g.z;
                    a = x.w * e.w; aa = a * a; s3 += aa; s1 += aa * g.w; s2 += aa * g.w * g.w;
                }
#pragma unroll
                for (int o = 16; o > 0; o >>= 1) {
                    s1 += __shfl_down_sync(0xFFFFFFFFu, s1, o);
                    s2 += __shfl_down_sync(0xFFFFFFFFu, s2, o);
                    s3 += __shfl_down_sync(0xFFFFFFFFu, s3, o);
                }
                if (lane == 0) {
                    const float eps = 1e-12f;
                    float n1 = fmaxf(sqrtf(s2), eps);
                    float n2 = fmaxf(sqrtf(s3), eps);
                    g_sim[(size_t)b * POOL + k] = s1 / (n1 * n2);
                }
            }
        }

        __threadfence();       // make g_sim stores device-visible
        __syncthreads();       // all warps done
        if (tid == 0) atomicAdd(&g_done, 1u);
        return;
    }

    // ================= pmt consumers =================
    if (tid == 0) {
        while (atomicAdd(&g_done, 0u) < SIM_BLOCKS) __nanosleep(64);
    }
    __syncthreads();
    __threadfence();           // acquire: see producers' g_sim stores

    const int b = blockIdx.x - (SIM_BLOCKS + COPY_BLOCKS);

    __shared__ float s_sim[POOL];
    if (tid < POOL)
        s_sim[tid] = g_sim[(size_t)b * POOL + tid];
    __syncthreads();

    const float4* ep4 = (const float4*)e_p;
    const size_t KEY4 = (size_t)BATCH * (PLEN / 2) * ED4;

    // PLEN*ED4 = 1536 float4 outputs per b; 256 threads -> 6 each
    for (int idx = tid; idx < PLEN * ED4; idx += 256) {
        int l  = idx / ED4;
        int d4 = idx % ED4;
        float4 acc = make_float4(0.f, 0.f, 0.f, 0.f);
        for (int kk = 0; kk < task_end; kk++) {
            float s  = s_sim[kk];
            float4 v = ep4[((size_t)kk * PLEN + l) * ED4 + d4];
            acc.x += s * v.x; acc.y += s * v.y;
            acc.z += s * v.z; acc.w += s * v.w;
        }
        float4* o4;
        if (l < PLEN / 2)
            o4 = (float4*)out + ((size_t)b * (PLEN / 2) + l) * ED4 + d4;
        else
            o4 = (float4*)out + KEY4 +
                 ((size_t)b * (PLEN / 2) + (l - PLEN / 2)) * ED4 + d4;
        *o4 = acc;
    }

    // Replay-safe reset: last pmt block to finish zeroes the counters.
    __syncthreads();
    if (tid == 0) {
        __threadfence();
        unsigned t = atomicAdd(&g_pmt_done, 1u);
        if (t == PMT_BLOCKS - 1) {
            atomicExch(&g_pmt_done, 0u);
            atomicExch(&g_done, 0u);
        }
    }
}

// ---------------------------------------------------------------------------
// Launch — one kernel, dependencies resolved in-kernel.
// Inputs (metadata order): x_querry, x_block, e_a, e_p, idx, task_id
// ---------------------------------------------------------------------------
extern "C" void kernel_launch(void* const* d_in, const int* in_sizes, int n_in,
                              void* d_out, int out_size) {
    const float* x_querry = (const float*)d_in[0];
    const float* x_block  = (const float*)d_in[1];
    const float* e_a      = (const float*)d_in[2];
    const float* e_p      = (const float*)d_in[3];
    const int*   task_id  = (const int*)d_in[5];
    float* out = (float*)d_out;

    size_t xb_float4s = (size_t)in_sizes[1] / 4;
    mega_kernel<<<SIM_BLOCKS + COPY_BLOCKS + PMT_BLOCKS, 256>>>(
        x_querry, e_a, e_p, x_block, task_id, out, xb_float4s);
}

// round 8
// speedup vs baseline: 1.0261x; 1.0061x over previous
#include <cuda_runtime.h>
#include <math.h>

// Problem constants (fixed by the reference)
#define POOL   100
#define NTASKS 10
#define NB_PT  (POOL / NTASKS)       // 10
#define PLEN   8
#define EMBD   768
#define BATCH  512
#define ED4    (EMBD / 4)            // 192

#define BG          8                // batch rows per sim block (one warp each)
#define COPY_BLOCKS 2560
#define PMT_BLOCKS  BATCH

// Scratch (allocation-free per harness rules)
__device__ float g_sim[BATCH * POOL];

// ---------------------------------------------------------------------------
// sim kernel (branch A, node 1): fused diag + sim. grid=(64,100), 8 warps.
// ---------------------------------------------------------------------------
__global__ void sim_fused_kernel(const float* __restrict__ x_querry,
                                 const float* __restrict__ e_a,
                                 const float* __restrict__ e_p,
                                 const int*   __restrict__ task_id_p) {
    const int task_end = (*task_id_p + 1) * NB_PT;
    const int k = blockIdx.y;
    if (k >= task_end) return;

    __shared__ float s_diag[EMBD];
    __shared__ float s_ea[EMBD];

    const float* epk = e_p + (size_t)k * PLEN * EMBD;
    for (int d = threadIdx.x; d < EMBD; d += 256) {
        float acc = 0.f;
#pragma unroll
        for (int l = 0; l < PLEN; l++) {
            float v = epk[l * EMBD + d];
            acc += v * v;
        }
        s_diag[d] = acc;
        s_ea[d]   = e_a[(size_t)k * EMBD + d];
    }
    __syncthreads();

    const int warp = threadIdx.x >> 5;
    const int lane = threadIdx.x & 31;
    const int b = blockIdx.x * BG + warp;
    const int row = POOL - task_end + k;

    const float4* xq4 = (const float4*)(x_querry + ((size_t)b * POOL + row) * EMBD);
    const float4* ea4 = (const float4*)s_ea;
    const float4* dg4 = (const float4*)s_diag;

    float s1 = 0.f, s2 = 0.f, s3 = 0.f;
#pragma unroll
    for (int j = 0; j < ED4 / 32; j++) {   // 6 iterations
        int idx = lane + j * 32;
        float4 x = xq4[idx];
        float4 e = ea4[idx];
        float4 g = dg4[idx];
        float a, aa;
        a = x.x * e.x; aa = a * a; s3 += aa; s1 += aa * g.x; s2 += aa * g.x * g.x;
        a = x.y * e.y; aa = a * a; s3 += aa; s1 += aa * g.y; s2 += aa * g.y * g.y;
        a = x.z * e.z; aa = a * a; s3 += aa; s1 += aa * g.z; s2 += aa * g.z * g.z;
        a = x.w * e.w; aa = a * a; s3 += aa; s1 += aa * g.w; s2 += aa * g.w * g.w;
    }
#pragma unroll
    for (int o = 16; o > 0; o >>= 1) {
        s1 += __shfl_down_sync(0xFFFFFFFFu, s1, o);
        s2 += __shfl_down_sync(0xFFFFFFFFu, s2, o);
        s3 += __shfl_down_sync(0xFFFFFFFFu, s3, o);
    }
    if (lane == 0) {
        const float eps = 1e-12f;
        float n1 = fmaxf(sqrtf(s2), eps);
        float n2 = fmaxf(sqrtf(s3), eps);
        g_sim[(size_t)b * POOL + k] = s1 / (n1 * n2);
    }
}

// ---------------------------------------------------------------------------
// pmt kernel (branch A, node 2): int_pmt[b,l,d] = sum_k sim[b,k]*e_p[k,l,d]
// ---------------------------------------------------------------------------
__global__ void pmt_kernel(const float* __restrict__ e_p,
                           const int*   __restrict__ task_id_p,
                           float* __restrict__ out) {
    const int task_end = (*task_id_p + 1) * NB_PT;
    const int b = blockIdx.x;

    __shared__ float s_sim[POOL];
    if (threadIdx.x < POOL)
        s_sim[threadIdx.x] = g_sim[(size_t)b * POOL + threadIdx.x];
    __syncthreads();

    const float4* ep4 = (const float4*)e_p;
    const size_t KEY4 = (size_t)BATCH * (PLEN / 2) * ED4;

    for (int idx = threadIdx.x; idx < PLEN * ED4; idx += 256) {
        int l  = idx / ED4;
        int d4 = idx % ED4;
        float4 acc = make_float4(0.f, 0.f, 0.f, 0.f);
        for (int kk = 0; kk < task_end; kk++) {
            float s  = s_sim[kk];
            float4 v = ep4[((size_t)kk * PLEN + l) * ED4 + d4];
            acc.x += s * v.x; acc.y += s * v.y;
            acc.z += s * v.z; acc.w += s * v.w;
        }
        float4* o4;
        if (l < PLEN / 2)
            o4 = (float4*)out + ((size_t)b * (PLEN / 2) + l) * ED4 + d4;
        else
            o4 = (float4*)out + KEY4 +
                 ((size_t)b * (PLEN / 2) + (l - PLEN / 2)) * ED4 + d4;
        *o4 = acc;
    }
}

// ---------------------------------------------------------------------------
// copy kernel (branch B): x_block -> out tail, evict-first streaming.
// ---------------------------------------------------------------------------
__global__ void __launch_bounds__(256) copy_kernel(
        const float* __restrict__ x_block,
        float* __restrict__ out,
        size_t xb_float4s) {
    const float4* src = (const float4*)x_block;
    float4* dst = (float4*)(out + (size_t)BATCH * PLEN * EMBD);

    const size_t stride = (size_t)COPY_BLOCKS * 256;
    size_t i = (size_t)blockIdx.x * 256 + threadIdx.x;

    // 4-way independent unroll (measured best: ~6.0 TB/s)
    for (; i + 3 * stride < xb_float4s; i += 4 * stride) {
        float4 v0 = __ldcs(src + i);
        float4 v1 = __ldcs(src + i + stride);
        float4 v2 = __ldcs(src + i + 2 * stride);
        float4 v3 = __ldcs(src + i + 3 * stride);
        __stcs(dst + i,              v0);
        __stcs(dst + i + stride,     v1);
        __stcs(dst + i + 2 * stride, v2);
        __stcs(dst + i + 3 * stride, v3);
    }
    for (; i < xb_float4s; i += stride)
        __stcs(dst + i, __ldcs(src + i));
}

// ---------------------------------------------------------------------------
// Launch — fork/join stream capture: (sim -> pmt) runs PARALLEL to copy.
//   main (legacy NULL) : ---e1---------------- copy ---------- wait(e2) ---
//   side stream        :  wait(e1) sim -> pmt  e2
// Inputs (metadata order): x_querry, x_block, e_a, e_p, idx, task_id
// ---------------------------------------------------------------------------
extern "C" void kernel_launch(void* const* d_in, const int* in_sizes, int n_in,
                              void* d_out, int out_size) {
    const float* x_querry = (const float*)d_in[0];
    const float* x_block  = (const float*)d_in[1];
    const float* e_a      = (const float*)d_in[2];
    const float* e_p      = (const float*)d_in[3];
    const int*   task_id  = (const int*)d_in[5];
    float* out = (float*)d_out;

    // One-time host-object setup (no device memory involved; identical GPU
    // work is issued on every call).
    static cudaStream_t s_side = nullptr;
    static cudaEvent_t  s_e1 = nullptr, s_e2 = nullptr;
    if (s_side == nullptr) {
        cudaStreamCreateWithFlags(&s_side, cudaStreamNonBlocking);
        cudaEventCreateWithFlags(&s_e1, cudaEventDisableTiming);
        cudaEventCreateWithFlags(&s_e2, cudaEventDisableTiming);
    }

    size_t xb_float4s = (size_t)in_sizes[1] / 4;

    // Fork side branch off the main (captured) stream.
    cudaEventRecord(s_e1, 0);
    cudaStreamWaitEvent(s_side, s_e1, 0);

    // Branch B (main stream): the big copy — starts immediately.
    copy_kernel<<<COPY_BLOCKS, 256>>>(x_block, out, xb_float4s);

    // Branch A (side stream): sim -> pmt, overlapped with the copy.
    dim3 sim_grid(BATCH / BG, POOL);
    sim_fused_kernel<<<sim_grid, 256, 0, s_side>>>(x_querry, e_a, e_p, task_id);
    pmt_kernel<<<PMT_BLOCKS, 256, 0, s_side>>>(e_p, task_id, out);

    // Join side branch back into the main stream.
    cudaEventRecord(s_e2, s_side);
    cudaStreamWaitEvent(0, s_e2, 0);
}